// round 17
// baseline (speedup 1.0000x reference)
#include <cuda_runtime.h>
#include <cuda_fp16.h>
#include <math.h>
#include <stdint.h>

#define B_SZ  64
#define DM    768
#define DI    1536
#define NS    16
#define LSEQ  256
#define RWS   16
#define DTR   48

// ---------------- scratch (static device arrays; no allocation) ----------------
__device__ __half g_xh[B_SZ * LSEQ * DI];         // (b, l, d) half
__device__ __half g_zh[B_SZ * LSEQ * DI];         // (b, l, d) half
__device__ __half g_xch[2][B_SZ * LSEQ * DI];     // conv+silu, half
__device__ float  g_xcomp[2][B_SZ * RWS * DI];    // (b, r, d)
__device__ float  g_xdbl[2][B_SZ * RWS * 80];     // (b, r, e)
__device__ float  g_y[2][B_SZ * RWS * DI];        // (b, r, d)
__device__ __half g_gated[B_SZ * LSEQ * DI];      // (b*l, d) half
__device__ __half g_hsh[B_SZ * LSEQ * DM];        // hidden_states half
__device__ __half g_wih[2 * DI * DM];             // in_proj_w half
__device__ __half g_woh[DM * DI];                 // out_proj_w half

// ---------------- helpers ----------------
__device__ __forceinline__ void mma_f16(float* c, const unsigned* a, const unsigned* b) {
    asm volatile(
        "mma.sync.aligned.m16n8k16.row.col.f32.f16.f16.f32 "
        "{%0,%1,%2,%3}, {%4,%5,%6,%7}, {%8,%9}, {%0,%1,%2,%3};"
        : "+f"(c[0]), "+f"(c[1]), "+f"(c[2]), "+f"(c[3])
        : "r"(a[0]), "r"(a[1]), "r"(a[2]), "r"(a[3]), "r"(b[0]), "r"(b[1]));
}
__device__ __forceinline__ void ldsm_x4(unsigned& r0, unsigned& r1, unsigned& r2, unsigned& r3,
                                        uint32_t addr) {
    asm volatile("ldmatrix.sync.aligned.m8n8.x4.shared.b16 {%0,%1,%2,%3}, [%4];"
                 : "=r"(r0), "=r"(r1), "=r"(r2), "=r"(r3) : "r"(addr));
}
__device__ __forceinline__ unsigned pack_half2(float x, float y) {
    __half2 h = __floats2half2_rn(x, y);
    return *(unsigned*)&h;
}
__device__ __forceinline__ void cp16(uint32_t dst, const void* src) {
    asm volatile("cp.async.cg.shared.global [%0], [%1], 16;" :: "r"(dst), "l"(src));
}
#define CP_COMMIT() asm volatile("cp.async.commit_group;" ::: "memory")
#define CP_WAIT0()  asm volatile("cp.async.wait_group 0;" ::: "memory")

// ---------------- fp32 -> fp16 convert (vectorized) ----------------
__global__ void __launch_bounds__(256) f2h_k(const float* __restrict__ src,
                                             __half* __restrict__ dst, int n4)
{
    const int i = blockIdx.x * 256 + threadIdx.x;
    if (i < n4) {
        float4 v = ((const float4*)src)[i];
        uint2 o;
        o.x = pack_half2(v.x, v.y);
        o.y = pack_half2(v.z, v.w);
        ((uint2*)dst)[i] = o;
    }
}

// ---------------- fp16 GEMM (BK=64, 2-stage, warp tile 64x64) ----------------
// Block 128(m) x 256(n), 256 threads = 8 warps (2m x 4n), warp tile 64x64.
// MODE 1: A=g_hsh, W=g_wih; epilogue -> g_xh / g_zh (half)   (K=768,  N=3072)
// MODE 2: A=g_gated, W=g_woh; C=out f32                       (K=1536, N=768)
#define HG_BK 64
#define HG_RS 72                                    // row stride in halves
#define HG_A_HALVES (128 * HG_RS)                   // 9216
#define HG_B_HALVES (256 * HG_RS)                   // 18432
#define HG_STAGE_HALVES (HG_A_HALVES + HG_B_HALVES) // 27648
#define HG_SMEM_BYTES (2 * HG_STAGE_HALVES * 2)     // 110592 B

template<int MODE>
__global__ void __launch_bounds__(256, 1) hgemm(float* __restrict__ C, int K)
{
    extern __shared__ __half sm[];
    // stage s: [A (128x72) | B (256x72)]
    const __half* Ah = (MODE == 1) ? (const __half*)g_hsh : (const __half*)g_gated;
    const __half* Wh = (MODE == 1) ? (const __half*)g_wih : (const __half*)g_woh;

    const int tid = threadIdx.x;
    const int warp = tid >> 5, lane = tid & 31;
    const int m0 = blockIdx.y * 128, n0 = blockIdx.x * 256;
    const int wm = (warp >> 2) * 64;       // 0 or 64
    const int wn = (warp & 3) * 64;        // 0..192
    const int grp = lane >> 2, tig = lane & 3;

    // ---- cp.async mapping ----
    const int lchunk = tid & 7;            // 16B chunk within 128B k-row
    const int lrow = tid >> 3;             // 0..31

    const __half* AbaseG = Ah + (size_t)(m0 + lrow) * K + lchunk * 8;
    const __half* BbaseG = Wh + (size_t)(n0 + lrow) * K + lchunk * 8;
    const size_t row32 = (size_t)32 * K;

    uint32_t a_cp[2], b_cp[2];
#pragma unroll
    for (int s = 0; s < 2; s++) {
        a_cp[s] = (uint32_t)__cvta_generic_to_shared(
            sm + s * HG_STAGE_HALVES + lrow * HG_RS + lchunk * 8);
        b_cp[s] = (uint32_t)__cvta_generic_to_shared(
            sm + s * HG_STAGE_HALVES + HG_A_HALVES + lrow * HG_RS + lchunk * 8);
    }
    const uint32_t grp_stride = 32 * HG_RS * 2;    // bytes per 32-row group

    // ---- ldmatrix addresses (stage 0, ks 0) ----
    const uint32_t a_lds0 = (uint32_t)__cvta_generic_to_shared(
        sm + ((wm + (lane & 15)) * HG_RS + 8 * (lane >> 4)));
    const uint32_t b_lds0 = (uint32_t)__cvta_generic_to_shared(
        sm + HG_A_HALVES + ((wn + ((lane >> 4) << 3) + (lane & 7)) * HG_RS + 8 * ((lane >> 3) & 1)));

    float acc[4][8][4];
#pragma unroll
    for (int i = 0; i < 4; i++)
#pragma unroll
        for (int j = 0; j < 8; j++)
#pragma unroll
            for (int r = 0; r < 4; r++) acc[i][j][r] = 0.f;

    const int NIT = K / HG_BK;

    // prologue: fill stage 0 (A: 4 groups, B: 8 groups)
#pragma unroll
    for (int g = 0; g < 4; g++)
        cp16(a_cp[0] + g * grp_stride, AbaseG + (size_t)g * row32);
#pragma unroll
    for (int g = 0; g < 8; g++)
        cp16(b_cp[0] + g * grp_stride, BbaseG + (size_t)g * row32);
    CP_COMMIT();

    for (int it = 0; it < NIT; ++it) {
        CP_WAIT0();
        __syncthreads();

        if (it + 1 < NIT) {
            const int ns = (it + 1) & 1;
            const int k0 = (it + 1) * HG_BK;
#pragma unroll
            for (int g = 0; g < 4; g++)
                cp16(a_cp[ns] + g * grp_stride, AbaseG + k0 + (size_t)g * row32);
#pragma unroll
            for (int g = 0; g < 8; g++)
                cp16(b_cp[ns] + g * grp_stride, BbaseG + k0 + (size_t)g * row32);
            CP_COMMIT();
        }

        const uint32_t stoff = (it & 1) * (HG_STAGE_HALVES * 2);
        const uint32_t a_st = a_lds0 + stoff;
        const uint32_t b_st = b_lds0 + stoff;
#pragma unroll
        for (int ks = 0; ks < 4; ks++) {
            const uint32_t kb = ks * 32;     // 16 halves = 32 B per k-step
            unsigned afr[4][4], bfr[8][2];
#pragma unroll
            for (int mt = 0; mt < 4; mt++)
                ldsm_x4(afr[mt][0], afr[mt][1], afr[mt][2], afr[mt][3],
                        a_st + mt * (16 * HG_RS * 2) + kb);
#pragma unroll
            for (int p = 0; p < 4; p++)
                ldsm_x4(bfr[2 * p][0], bfr[2 * p][1], bfr[2 * p + 1][0], bfr[2 * p + 1][1],
                        b_st + p * (16 * HG_RS * 2) + kb);
#pragma unroll
            for (int mt = 0; mt < 4; mt++)
#pragma unroll
                for (int nt = 0; nt < 8; nt++)
                    mma_f16(acc[mt][nt], afr[mt], bfr[nt]);
        }
    }

    // epilogue
#pragma unroll
    for (int mt = 0; mt < 4; mt++) {
#pragma unroll
        for (int nt = 0; nt < 8; nt++) {
            const int m = m0 + wm + mt * 16 + grp;
            const int n = n0 + wn + nt * 8 + 2 * tig;
            if (MODE == 1) {
                __half* dst = (n0 < DI) ? g_xh : g_zh;
                const int nn = (n0 < DI) ? n : (n - DI);
                *(unsigned*)&dst[(size_t)m * DI + nn] = pack_half2(acc[mt][nt][0], acc[mt][nt][1]);
                *(unsigned*)&dst[(size_t)(m + 8) * DI + nn] = pack_half2(acc[mt][nt][2], acc[mt][nt][3]);
            } else {
                *(float2*)&C[(size_t)m * 768 + n] = make_float2(acc[mt][nt][0], acc[mt][nt][1]);
                *(float2*)&C[(size_t)(m + 8) * 768 + n] = make_float2(acc[mt][nt][2], acc[mt][nt][3]);
            }
        }
    }
}

// ---------------- conv + SiLU + 16-block mean (both directions, tiled) ----------------
__global__ void __launch_bounds__(256) conv_silu_k(const float* __restrict__ cw,
                                                   const float* __restrict__ cb,
                                                   const float* __restrict__ cwb,
                                                   const float* __restrict__ cbb)
{
    __shared__ float X[256][17];
    __shared__ float F[256][17];

    const int d0 = blockIdx.x * 16;
    const int b = blockIdx.y;
    const int tid = threadIdx.x;

    // load X tile from half g_xh: 256 l x 16 d
#pragma unroll
    for (int i = 0; i < 2; i++) {
        const int idx = tid + 256 * i;      // 0..511 (16B chunks of 8 halves)
        const int l = idx >> 1, h8 = idx & 1;
        uint4 v = *(const uint4*)&g_xh[((size_t)b * LSEQ + l) * DI + d0 + 8 * h8];
        const __half* hp = (const __half*)&v;
#pragma unroll
        for (int k = 0; k < 8; k++) X[l][8 * h8 + k] = __half2float(hp[k]);
    }
    __syncthreads();

    const int sub = tid >> 4;
    const int d = tid & 15;
    const int dg = d0 + d;

    {
        float w[4];
#pragma unroll
        for (int k = 0; k < 4; k++) w[k] = cw[dg * 4 + k];
        const float bias = cb[dg];
#pragma unroll
        for (int i = 0; i < 16; i++) {
            const int l = i * 16 + sub;
            float a = bias;
#pragma unroll
            for (int k = 0; k < 4; k++) {
                const int idx = l - 3 + k;
                if (idx >= 0) a += w[k] * X[idx][d];
            }
            const float s = __fdividef(a, 1.f + __expf(-a));
            F[l][d] = s;
            g_xch[0][((size_t)b * LSEQ + l) * DI + dg] = __float2half_rn(s);
        }
    }
    __syncthreads();
    {
        const int r = tid >> 4;
        float s = 0.f;
#pragma unroll
        for (int j = 0; j < 16; j++) s += F[16 * r + j][d];
        g_xcomp[0][((size_t)b * RWS + r) * DI + dg] = s * (1.f / 16.f);
    }
    __syncthreads();

    {
        float w[4];
#pragma unroll
        for (int k = 0; k < 4; k++) w[k] = cwb[dg * 4 + k];
        const float bias = cbb[dg];
#pragma unroll
        for (int i = 0; i < 16; i++) {
            const int l = i * 16 + sub;
            float a = bias;
#pragma unroll
            for (int k = 0; k < 4; k++) {
                const int idx = l - 3 + k;
                if (idx >= 0) a += w[k] * X[255 - idx][d];
            }
            const float s = __fdividef(a, 1.f + __expf(-a));
            F[l][d] = s;
            g_xch[1][((size_t)b * LSEQ + l) * DI + dg] = __float2half_rn(s);
        }
    }
    __syncthreads();
    {
        const int r = tid >> 4;
        float s = 0.f;
#pragma unroll
        for (int j = 0; j < 16; j++) s += F[16 * r + j][d];
        g_xcomp[1][((size_t)b * RWS + r) * DI + dg] = s * (1.f / 16.f);
    }
}

// ---------------- x_proj: 4 r per block ----------------
__global__ void __launch_bounds__(256) xdbl_k(const float* __restrict__ xpw_f,
                                              const float* __restrict__ xpw_b)
{
    __shared__ float xs[4 * DI];
    const int dir = blockIdx.y;
    const int b = blockIdx.x >> 2;
    const int rq = blockIdx.x & 3;

    const float* src = g_xcomp[dir] + ((size_t)b * RWS + rq * 4) * DI;
    for (int i = threadIdx.x; i < 4 * DI; i += 256) xs[i] = src[i];
    __syncthreads();

    const float* xpw = dir ? xpw_b : xpw_f;
    const int warp = threadIdx.x >> 5, lane = threadIdx.x & 31;
    for (int e = warp; e < 80; e += 8) {
        const float* wrow = xpw + (size_t)e * DI;
        float s0 = 0.f, s1 = 0.f, s2 = 0.f, s3 = 0.f;
        for (int k = lane; k < DI; k += 32) {
            const float w = wrow[k];
            s0 += w * xs[k];
            s1 += w * xs[DI + k];
            s2 += w * xs[2 * DI + k];
            s3 += w * xs[3 * DI + k];
        }
#pragma unroll
        for (int off = 16; off >= 1; off >>= 1) {
            s0 += __shfl_xor_sync(0xffffffffu, s0, off);
            s1 += __shfl_xor_sync(0xffffffffu, s1, off);
            s2 += __shfl_xor_sync(0xffffffffu, s2, off);
            s3 += __shfl_xor_sync(0xffffffffu, s3, off);
        }
        if (lane < 4) {
            const float v = (lane == 0) ? s0 : (lane == 1) ? s1 : (lane == 2) ? s2 : s3;
            g_xdbl[dir][((size_t)b * RWS + rq * 4 + lane) * 80 + e] = v;
        }
    }
}

// ---------------- fused dt_proj + softplus + selective scan ----------------
__global__ void __launch_bounds__(128) scan_k(const float* __restrict__ dtw_f,
                                              const float* __restrict__ dtw_b,
                                              const float* __restrict__ dtb_f,
                                              const float* __restrict__ dtb_b,
                                              const float* __restrict__ Alog_f,
                                              const float* __restrict__ Alog_b)
{
    __shared__ float xd[RWS * 80];
    __shared__ float dtws[128][49];

    const int dir = blockIdx.z;
    const int b = blockIdx.y;
    const int d0 = blockIdx.x * 128;
    const int tid = threadIdx.x;
    const int d = d0 + tid;

    const float* xdbl = g_xdbl[dir] + (size_t)b * RWS * 80;
    for (int i = tid; i < RWS * 80; i += 128) xd[i] = xdbl[i];

    const float* dtw = dir ? dtw_b : dtw_f;
    for (int idx = tid; idx < 128 * DTR; idx += 128) {
        const int row = idx / DTR, col = idx % DTR;
        dtws[row][col] = dtw[(size_t)d0 * DTR + idx];
    }
    __syncthreads();

    const float* Alog = (dir ? Alog_b : Alog_f) + (size_t)d * NS;
    const float bias = dir ? dtb_b[d] : dtb_f[d];

    float A[NS];
#pragma unroll
    for (int n = 0; n < NS; n++) A[n] = -expf(Alog[n]);

    const float A0 = A[0];
    bool chain = true;
#pragma unroll
    for (int n = 1; n < NS; n++)
        chain = chain && (fabsf(A[n] - (float)(n + 1) * A0) <= 1e-4f * fabsf(A[n]));

    float u[RWS];
    const float* up = g_xcomp[dir] + (size_t)b * RWS * DI + d;
#pragma unroll
    for (int r = 0; r < RWS; r++) u[r] = up[(size_t)r * DI];

    float h[NS];
#pragma unroll
    for (int n = 0; n < NS; n++) h[n] = 0.f;

    float* yp = g_y[dir] + (size_t)b * RWS * DI + d;
#pragma unroll 1
    for (int r = 0; r < RWS; r++) {
        float dt = bias;
#pragma unroll
        for (int rr = 0; rr < DTR; rr++) dt += xd[r * 80 + rr] * dtws[tid][rr];
        const float delta = fmaxf(dt, 0.f) + log1pf(__expf(-fabsf(dt)));
        const float du = delta * u[r];
        const float qch = __expf(delta * A0);
        float p = 1.f;
        float acc = 0.f;
#pragma unroll
        for (int n = 0; n < NS; n++) {
            float dA;
            if (chain) { p *= qch; dA = p; }
            else       { dA = __expf(delta * A[n]); }
            h[n] = dA * h[n] + du * xd[r * 80 + 48 + n];
            acc += h[n] * xd[r * 80 + 64 + n];
        }
        yp[(size_t)r * DI] = acc;
    }
}

// ---------------- combine + LayerNorm + SiLU(z) gate ----------------
__global__ void __launch_bounds__(256) ln_gate_k(const float* __restrict__ Dp,
                                                 const float* __restrict__ Dpb,
                                                 const float* __restrict__ gamma,
                                                 const float* __restrict__ beta)
{
    const int bl = blockIdx.x;
    const int b = bl >> 8;
    const int l = bl & 255;
    const int lb = 255 - l;
    const int rf = l >> 4, rb = lb >> 4;
    const int tid = threadIdx.x;

    const __half* xcf = g_xch[0] + ((size_t)b * LSEQ + l) * DI;
    const __half* xcb = g_xch[1] + ((size_t)b * LSEQ + lb) * DI;
    const float* yf = g_y[0] + ((size_t)b * RWS + rf) * DI;
    const float* yb = g_y[1] + ((size_t)b * RWS + rb) * DI;

    float v[6];
    float s = 0.f, s2 = 0.f;
#pragma unroll
    for (int i = 0; i < 6; i++) {
        const int d = tid + i * 256;
        const float cf = yf[d] + Dp[d] * __half2float(xcf[d]);
        const float cbv = yb[d] + Dpb[d] * __half2float(xcb[d]);
        const float val = 0.5f * (cf + cbv);
        v[i] = val;
        s += val;
        s2 += val * val;
    }

    __shared__ float red[16];
#pragma unroll
    for (int off = 16; off >= 1; off >>= 1) {
        s += __shfl_xor_sync(0xffffffffu, s, off);
        s2 += __shfl_xor_sync(0xffffffffu, s2, off);
    }
    const int warp = tid >> 5, lane = tid & 31;
    if (lane == 0) { red[warp] = s; red[warp + 8] = s2; }
    __syncthreads();
    if (warp == 0) {
        float a = (lane < 8) ? red[lane] : 0.f;
        float c = (lane < 8) ? red[lane + 8] : 0.f;
#pragma unroll
        for (int off = 4; off >= 1; off >>= 1) {
            a += __shfl_xor_sync(0xffffffffu, a, off);
            c += __shfl_xor_sync(0xffffffffu, c, off);
        }
        if (lane == 0) { red[0] = a; red[1] = c; }
    }
    __syncthreads();

    const float mean = red[0] * (1.f / DI);
    const float var = red[1] * (1.f / DI) - mean * mean;
    const float rstd = rsqrtf(var + 1e-5f);

#pragma unroll
    for (int i = 0; i < 6; i++) {
        const int d = tid + i * 256;
        const float g = (v[i] - mean) * rstd * gamma[d] + beta[d];
        const float zv = __half2float(g_zh[(size_t)bl * DI + d]);
        const float sz = __fdividef(zv, 1.f + __expf(-zv));
        g_gated[(size_t)bl * DI + d] = __float2half_rn(g * sz);
    }
}

// ---------------- launch ----------------
extern "C" void kernel_launch(void* const* d_in, const int* in_sizes, int n_in,
                              void* d_out, int out_size)
{
    const float* hs    = (const float*)d_in[0];
    const float* inw   = (const float*)d_in[1];
    const float* cw    = (const float*)d_in[2];
    const float* cb    = (const float*)d_in[3];
    const float* cwb   = (const float*)d_in[4];
    const float* cbb   = (const float*)d_in[5];
    const float* xpw   = (const float*)d_in[6];
    const float* xpwb  = (const float*)d_in[7];
    const float* dtw   = (const float*)d_in[8];
    const float* dtwb  = (const float*)d_in[9];
    const float* dtb   = (const float*)d_in[10];
    const float* dtbb  = (const float*)d_in[11];
    const float* Alog  = (const float*)d_in[12];
    const float* Alogb = (const float*)d_in[13];
    const float* Dp    = (const float*)d_in[14];
    const float* Dpb   = (const float*)d_in[15];
    const float* gam   = (const float*)d_in[16];
    const float* bet   = (const float*)d_in[17];
    const float* opw   = (const float*)d_in[18];
    float* out = (float*)d_out;

    __half *d_hsh, *d_wih, *d_woh;
    cudaGetSymbolAddress((void**)&d_hsh, g_hsh);
    cudaGetSymbolAddress((void**)&d_wih, g_wih);
    cudaGetSymbolAddress((void**)&d_woh, g_woh);

    cudaFuncSetAttribute(hgemm<1>, cudaFuncAttributeMaxDynamicSharedMemorySize, HG_SMEM_BYTES);
    cudaFuncSetAttribute(hgemm<2>, cudaFuncAttributeMaxDynamicSharedMemorySize, HG_SMEM_BYTES);

    // 0) convert fp32 inputs to half
    {
        const int n1 = B_SZ * LSEQ * DM / 4;      // hs
        const int n2 = 2 * DI * DM / 4;           // in_proj_w
        const int n3 = DM * DI / 4;               // out_proj_w
        f2h_k<<<(n1 + 255) / 256, 256>>>(hs, d_hsh, n1);
        f2h_k<<<(n2 + 255) / 256, 256>>>(inw, d_wih, n2);
        f2h_k<<<(n3 + 255) / 256, 256>>>(opw, d_woh, n3);
    }
    // 1) in_proj: (16384 x 768) x (3072 x 768)^T -> g_xh | g_zh
    hgemm<1><<<dim3(3072 / 256, 16384 / 128), 256, HG_SMEM_BYTES>>>(nullptr, DM);
    // 2) depthwise conv + SiLU + block means
    conv_silu_k<<<dim3(DI / 16, B_SZ), 256>>>(cw, cb, cwb, cbb);
    // 3) x_proj
    xdbl_k<<<dim3(B_SZ * 4, 2), 256>>>(xpw, xpwb);
    // 4) dt_proj + selective scan
    scan_k<<<dim3(DI / 128, B_SZ, 2), 128>>>(dtw, dtwb, dtb, dtbb, Alog, Alogb);
    // 5) combine + LN + gate
    ln_gate_k<<<B_SZ * LSEQ, 256>>>(Dp, Dpb, gam, bet);
    // 6) out_proj: (16384 x 1536) x (768 x 1536)^T -> d_out
    hgemm<2><<<dim3(768 / 256, 16384 / 128), 256, HG_SMEM_BYTES>>>(out, DI);
}